// round 4
// baseline (speedup 1.0000x reference)
#include <cuda_runtime.h>
#include <cuda_bf16.h>
#include <mma.h>
#include <math.h>
#include <stdint.h>

using namespace nvcuda;

// Problem constants: N=100000, F=256, UNITS=256, DIM=128
#define F_DIM   256
#define UNITS   256
#define DIM     128
#define N_MAX   100000
#define M_TILE  64

// Scratch
__device__ float         g_x[(size_t)N_MAX * UNITS];   // ~102.4 MB
__device__ int           g_rowptr[N_MAX + 1];
__device__ float         g_kl;
__device__ __nv_bfloat16 g_Wh[UNITS * F_DIM];          // W^T hi, [n][k] (k contiguous)
__device__ __nv_bfloat16 g_Wl[UNITS * F_DIM];          // W^T lo, [n][k]

// ---------------------------------------------------------------------------
// MUFU-free exp for x <= 0 (exponent-bit scaling + degree-7 poly for 2^f)
// ---------------------------------------------------------------------------
__device__ __forceinline__ float fast_exp(float x) {
    x = fmaxf(x, -80.f);
    const float t = x * 1.4426950408889634f;
    const float nf = rintf(t);
    const float f = t - nf;
    float p = 1.5253232e-5f;
    p = fmaf(p, f, 1.54035304e-4f);
    p = fmaf(p, f, 1.33335581e-3f);
    p = fmaf(p, f, 9.61812911e-3f);
    p = fmaf(p, f, 5.55041087e-2f);
    p = fmaf(p, f, 2.40226507e-1f);
    p = fmaf(p, f, 6.93147181e-1f);
    p = fmaf(p, f, 1.0f);
    return __int_as_float(__float_as_int(p) + (((int)nf) << 23));
}
// elu via expm1: x*P(x) for small |x| (no cancellation), exp-1 otherwise
__device__ __forceinline__ float elu_f(float x) {
    if (x > 0.f) return x;
    if (x > -0.5f) {
        float p = 1.98412698e-4f;         // 1/5040
        p = fmaf(p, x, 1.38888889e-3f);   // 1/720
        p = fmaf(p, x, 8.33333333e-3f);   // 1/120
        p = fmaf(p, x, 4.16666667e-2f);   // 1/24
        p = fmaf(p, x, 1.66666667e-1f);   // 1/6
        p = fmaf(p, x, 0.5f);
        p = fmaf(p, x, 1.0f);
        return x * p;
    }
    return fast_exp(x) - 1.0f;
}

// ---------------------------------------------------------------------------
// Kernel 1: CSR row_ptr via boundary scatter (row[] sorted)
// ---------------------------------------------------------------------------
__global__ void build_rowptr_kernel(const int* __restrict__ row, int n, int e) {
    int i = blockIdx.x * blockDim.x + threadIdx.x;
    if (i == 0) g_kl = 0.0f;
    if (i > e) return;
    int prev = (i == 0) ? -1 : row[i - 1];
    int cur  = (i == e) ? n  : row[i];
    for (int j = prev + 1; j <= cur; j++) g_rowptr[j] = i;
}

// ---------------------------------------------------------------------------
// Kernel 1b: split W (fp32 [K,N]) into transposed bf16 hi/lo [N,K]
// ---------------------------------------------------------------------------
__global__ void wsplit_kernel(const float* __restrict__ W) {
    int i = blockIdx.x * blockDim.x + threadIdx.x;
    if (i >= UNITS * F_DIM) return;
    const int nn = i / F_DIM, kk = i % F_DIM;
    const float w = W[kk * UNITS + nn];
    const __nv_bfloat16 h = __float2bfloat16(w);
    g_Wh[i] = h;
    g_Wl[i] = __float2bfloat16(w - __bfloat162float(h));
}

// ---------------------------------------------------------------------------
// Kernel 2: WMMA bf16x3 GEMM + fused epilogue.
// CTA: 256 threads (8 warps). M_TILE=64 rows, N=256 full, K=256.
// Warp w: row-group rg = w>>2 (2 x 32 rows), col-group cg = w&3 (4 x 64 cols)
//   -> each warp: 2x4 accum tiles of 16x16 (32 rows x 64 cols).
// SMEM: Ah[64][256] + Al[64][256] bf16 (64KB), reused as C[64][256] fp32.
// ---------------------------------------------------------------------------
__global__ __launch_bounds__(256, 1) void gemm_wmma_kernel(
    const float* __restrict__ feat, int n)
{
    extern __shared__ char smem[];
    __nv_bfloat16* Ah = reinterpret_cast<__nv_bfloat16*>(smem);           // 32KB
    __nv_bfloat16* Al = Ah + M_TILE * F_DIM;                              // 32KB
    float* C = reinterpret_cast<float*>(smem);                            // reuse

    const int tid = threadIdx.x;
    const int wid = tid >> 5, lane = tid & 31;
    const int row0 = blockIdx.x * M_TILE;
    const int nrows = min(M_TILE, n - row0);

    // --- stage A: fp32 -> bf16 hi/lo in smem ---
#pragma unroll
    for (int it = 0; it < 16; it++) {
        const int j = it * 256 + tid;          // float4 id, 0..4095
        const int r = j >> 6;                  // row 0..63
        const int c4 = (j & 63) << 2;          // col 0,4,..252
        float4 v = make_float4(0.f, 0.f, 0.f, 0.f);
        if (r < nrows)
            v = reinterpret_cast<const float4*>(feat + (size_t)(row0 + r) * F_DIM)[j & 63];
        const __nv_bfloat16 h0 = __float2bfloat16(v.x);
        const __nv_bfloat16 h1 = __float2bfloat16(v.y);
        const __nv_bfloat16 h2 = __float2bfloat16(v.z);
        const __nv_bfloat16 h3 = __float2bfloat16(v.w);
        __nv_bfloat162 ph0; ph0.x = h0; ph0.y = h1;
        __nv_bfloat162 ph1; ph1.x = h2; ph1.y = h3;
        __nv_bfloat162 pl0, pl1;
        pl0.x = __float2bfloat16(v.x - __bfloat162float(h0));
        pl0.y = __float2bfloat16(v.y - __bfloat162float(h1));
        pl1.x = __float2bfloat16(v.z - __bfloat162float(h2));
        pl1.y = __float2bfloat16(v.w - __bfloat162float(h3));
        reinterpret_cast<__nv_bfloat162*>(Ah + r * F_DIM + c4)[0] = ph0;
        reinterpret_cast<__nv_bfloat162*>(Ah + r * F_DIM + c4)[1] = ph1;
        reinterpret_cast<__nv_bfloat162*>(Al + r * F_DIM + c4)[0] = pl0;
        reinterpret_cast<__nv_bfloat162*>(Al + r * F_DIM + c4)[1] = pl1;
    }
    __syncthreads();

    // --- mainloop ---
    const int rg = wid >> 2;            // 0..1
    const int cg = wid & 3;             // 0..3

    wmma::fragment<wmma::accumulator, 16, 16, 16, float> acc[2][4];
#pragma unroll
    for (int i = 0; i < 2; i++)
#pragma unroll
        for (int j = 0; j < 4; j++) wmma::fill_fragment(acc[i][j], 0.0f);

#pragma unroll 2
    for (int k = 0; k < F_DIM; k += 16) {
        wmma::fragment<wmma::matrix_a, 16, 16, 16, __nv_bfloat16, wmma::row_major> fah[2], fal[2];
#pragma unroll
        for (int i = 0; i < 2; i++) {
            const int r = rg * 32 + i * 16;
            wmma::load_matrix_sync(fah[i], Ah + r * F_DIM + k, F_DIM);
            wmma::load_matrix_sync(fal[i], Al + r * F_DIM + k, F_DIM);
        }
#pragma unroll
        for (int j = 0; j < 4; j++) {
            const int ncol = cg * 64 + j * 16;
            wmma::fragment<wmma::matrix_b, 16, 16, 16, __nv_bfloat16, wmma::col_major> fbh, fbl;
            wmma::load_matrix_sync(fbh, g_Wh + (size_t)ncol * F_DIM + k, F_DIM);
            wmma::load_matrix_sync(fbl, g_Wl + (size_t)ncol * F_DIM + k, F_DIM);
#pragma unroll
            for (int i = 0; i < 2; i++) {
                wmma::mma_sync(acc[i][j], fah[i], fbh, acc[i][j]);
                wmma::mma_sync(acc[i][j], fah[i], fbl, acc[i][j]);
                wmma::mma_sync(acc[i][j], fal[i], fbh, acc[i][j]);
            }
        }
    }
    __syncthreads();   // A smem no longer needed; reuse as C

#pragma unroll
    for (int i = 0; i < 2; i++)
#pragma unroll
        for (int j = 0; j < 4; j++)
            wmma::store_matrix_sync(C + (rg * 32 + i * 16) * UNITS + cg * 64 + j * 16,
                                    acc[i][j], UNITS, wmma::mem_row_major);
    __syncthreads();

    // --- epilogue: activations, attention, KL, g_x ---
    float kl = 0.f;
#pragma unroll
    for (int it = 0; it < 32; it++) {
        const int idx = it * 256 + tid;        // 0..8191
        const int r = idx >> 7;                // 0..63
        const int d = idx & 127;
        if (r < nrows) {
            const float hm = C[r * UNITS + d];
            const float hv = C[r * UNITS + DIM + d];
            const float m = elu_f(hm);
            const float v = hv > 0.f ? hv : 0.f;
            const float att = fast_exp(-v);
            kl += m * m + v - logf(1e-8f + v) - 1.f;
            const size_t base = (size_t)(row0 + r) * UNITS;
            g_x[base + d]       = m * att;
            g_x[base + DIM + d] = v * att * att;
        }
    }
    kl *= 0.5f / (float)DIM;

    __shared__ float kl_red[8];
#pragma unroll
    for (int off = 16; off > 0; off >>= 1)
        kl += __shfl_down_sync(0xFFFFFFFFu, kl, off);
    if (lane == 0) kl_red[wid] = kl;
    __syncthreads();
    if (tid == 0) {
        float s = 0.f;
#pragma unroll
        for (int i = 0; i < 8; i++) s += kl_red[i];
        atomicAdd(&g_kl, s);
    }
}

// ---------------------------------------------------------------------------
// Kernel 3: fused dual SpMM, 2 warps per node, 4-way unrolled gathers
// ---------------------------------------------------------------------------
__global__ void spmm_kernel(
    const int* __restrict__ col,
    const float* __restrict__ a1,
    const float* __restrict__ a2,
    float* __restrict__ out,
    int n, int write_kl)
{
    const int gtid = blockIdx.x * blockDim.x + threadIdx.x;
    if (gtid == 0 && write_kl) out[(size_t)n * UNITS] = g_kl;

    const int work = gtid >> 5;
    const int node = work >> 1;
    const int half = work & 1;
    const int lane = threadIdx.x & 31;
    if (node >= n) return;

    const int s = g_rowptr[node];
    const int e = g_rowptr[node + 1];
    const float* __restrict__ av = half ? a2 : a1;
    const float* __restrict__ xb = g_x + half * DIM;

    float4 acc = make_float4(0.f, 0.f, 0.f, 0.f);
    int i = s;
    for (; i + 3 < e; i += 4) {
        const int c0 = __ldg(&col[i + 0]);
        const int c1 = __ldg(&col[i + 1]);
        const int c2 = __ldg(&col[i + 2]);
        const int c3 = __ldg(&col[i + 3]);
        const float w0 = __ldg(&av[i + 0]);
        const float w1 = __ldg(&av[i + 1]);
        const float w2 = __ldg(&av[i + 2]);
        const float w3 = __ldg(&av[i + 3]);
        const float4 x0 = __ldg(&reinterpret_cast<const float4*>(xb + (size_t)c0 * UNITS)[lane]);
        const float4 x1 = __ldg(&reinterpret_cast<const float4*>(xb + (size_t)c1 * UNITS)[lane]);
        const float4 x2 = __ldg(&reinterpret_cast<const float4*>(xb + (size_t)c2 * UNITS)[lane]);
        const float4 x3 = __ldg(&reinterpret_cast<const float4*>(xb + (size_t)c3 * UNITS)[lane]);
        acc.x = fmaf(w0, x0.x, acc.x); acc.y = fmaf(w0, x0.y, acc.y);
        acc.z = fmaf(w0, x0.z, acc.z); acc.w = fmaf(w0, x0.w, acc.w);
        acc.x = fmaf(w1, x1.x, acc.x); acc.y = fmaf(w1, x1.y, acc.y);
        acc.z = fmaf(w1, x1.z, acc.z); acc.w = fmaf(w1, x1.w, acc.w);
        acc.x = fmaf(w2, x2.x, acc.x); acc.y = fmaf(w2, x2.y, acc.y);
        acc.z = fmaf(w2, x2.z, acc.z); acc.w = fmaf(w2, x2.w, acc.w);
        acc.x = fmaf(w3, x3.x, acc.x); acc.y = fmaf(w3, x3.y, acc.y);
        acc.z = fmaf(w3, x3.z, acc.z); acc.w = fmaf(w3, x3.w, acc.w);
    }
    for (; i < e; i++) {
        const int c0 = __ldg(&col[i]);
        const float w0 = __ldg(&av[i]);
        const float4 x0 = __ldg(&reinterpret_cast<const float4*>(xb + (size_t)c0 * UNITS)[lane]);
        acc.x = fmaf(w0, x0.x, acc.x); acc.y = fmaf(w0, x0.y, acc.y);
        acc.z = fmaf(w0, x0.z, acc.z); acc.w = fmaf(w0, x0.w, acc.w);
    }
    reinterpret_cast<float4*>(out + (size_t)node * UNITS + half * DIM)[lane] = acc;
}

// ---------------------------------------------------------------------------
extern "C" void kernel_launch(void* const* d_in, const int* in_sizes, int n_in,
                              void* d_out, int out_size) {
    const float* feat = (const float*)d_in[0];
    const float* W    = (const float*)d_in[1];
    const int*   row  = (const int*)d_in[2];
    const int*   col  = (const int*)d_in[3];
    const float* a1   = (const float*)d_in[4];
    const float* a2   = (const float*)d_in[5];
    float* out = (float*)d_out;

    const int n = in_sizes[0] / F_DIM;
    const int e = in_sizes[2];
    const int write_kl = (out_size > n * UNITS) ? 1 : 0;

    {   // CSR row pointers
        const int threads = 256;
        build_rowptr_kernel<<<(e + 1 + threads - 1) / threads, threads>>>(row, n, e);
    }
    {   // W split to bf16 hi/lo, transposed
        const int threads = 256;
        wsplit_kernel<<<(UNITS * F_DIM + threads - 1) / threads, threads>>>(W);
    }
    {   // WMMA GEMM + epilogue (64KB dynamic smem)
        const int smem_total = M_TILE * F_DIM * sizeof(float);   // 65536
        static int attr_set = 0;
        if (!attr_set) {
            cudaFuncSetAttribute(gemm_wmma_kernel,
                                 cudaFuncAttributeMaxDynamicSharedMemorySize, smem_total);
            attr_set = 1;
        }
        gemm_wmma_kernel<<<(n + M_TILE - 1) / M_TILE, 256, smem_total>>>(feat, n);
    }
    {   // dual SpMM
        const int threads = 256;
        const int warps_needed = 2 * n;
        spmm_kernel<<<(warps_needed + 7) / 8, threads>>>(col, a1, a2, out, n, write_kl);
    }
}

// round 5
// speedup vs baseline: 1.5094x; 1.5094x over previous
#include <cuda_runtime.h>
#include <cuda_bf16.h>
#include <mma.h>
#include <math.h>
#include <stdint.h>

using namespace nvcuda;

// Problem constants: N=100000, F=256, UNITS=256, DIM=128
#define F_DIM   256
#define UNITS   256
#define DIM     128
#define N_MAX   100000
#define M_TILE  64
#define LDA     264          // padded A smem leading dim (elements)
#define LDB     72           // padded B smem leading dim (elements)
#define KC      64           // K chunk staged per iteration

// Scratch
__device__ float         g_x[(size_t)N_MAX * UNITS];   // ~102.4 MB
__device__ int           g_rowptr[N_MAX + 1];
__device__ float         g_kl;
__device__ __nv_bfloat16 g_Wh[UNITS * F_DIM];          // W^T hi, [n][k]
__device__ __nv_bfloat16 g_Wl[UNITS * F_DIM];          // W^T lo, [n][k]

// ---------------------------------------------------------------------------
// MUFU-free exp (x <= 0) and elu
// ---------------------------------------------------------------------------
__device__ __forceinline__ float fast_exp(float x) {
    x = fmaxf(x, -80.f);
    const float t = x * 1.4426950408889634f;
    const float nf = rintf(t);
    const float f = t - nf;
    float p = 1.5253232e-5f;
    p = fmaf(p, f, 1.54035304e-4f);
    p = fmaf(p, f, 1.33335581e-3f);
    p = fmaf(p, f, 9.61812911e-3f);
    p = fmaf(p, f, 5.55041087e-2f);
    p = fmaf(p, f, 2.40226507e-1f);
    p = fmaf(p, f, 6.93147181e-1f);
    p = fmaf(p, f, 1.0f);
    return __int_as_float(__float_as_int(p) + (((int)nf) << 23));
}
__device__ __forceinline__ float elu_f(float x) {
    if (x > 0.f) return x;
    if (x > -0.5f) {
        float p = 1.98412698e-4f;
        p = fmaf(p, x, 1.38888889e-3f);
        p = fmaf(p, x, 8.33333333e-3f);
        p = fmaf(p, x, 4.16666667e-2f);
        p = fmaf(p, x, 1.66666667e-1f);
        p = fmaf(p, x, 0.5f);
        p = fmaf(p, x, 1.0f);
        return x * p;
    }
    return fast_exp(x) - 1.0f;
}

// ---------------------------------------------------------------------------
// Kernel 1: CSR row_ptr via boundary scatter
// ---------------------------------------------------------------------------
__global__ void build_rowptr_kernel(const int* __restrict__ row, int n, int e) {
    int i = blockIdx.x * blockDim.x + threadIdx.x;
    if (i == 0) g_kl = 0.0f;
    if (i > e) return;
    int prev = (i == 0) ? -1 : row[i - 1];
    int cur  = (i == e) ? n  : row[i];
    for (int j = prev + 1; j <= cur; j++) g_rowptr[j] = i;
}

// ---------------------------------------------------------------------------
// Kernel 1b: split W (fp32 [K,N]) into transposed bf16 hi/lo [N,K]
// ---------------------------------------------------------------------------
__global__ void wsplit_kernel(const float* __restrict__ W) {
    int i = blockIdx.x * blockDim.x + threadIdx.x;
    if (i >= UNITS * F_DIM) return;
    const int nn = i / F_DIM, kk = i % F_DIM;
    const float w = W[kk * UNITS + nn];
    const __nv_bfloat16 h = __float2bfloat16(w);
    g_Wh[i] = h;
    g_Wl[i] = __float2bfloat16(w - __bfloat162float(h));
}

// ---------------------------------------------------------------------------
// Kernel 2: WMMA bf16x3 GEMM, B staged in smem per K-chunk, padded layouts.
// CTA: 256 threads (8 warps); M_TILE=64 rows; warp (rg=wid>>2, cg=wid&3)
// owns 32 rows x 64 cols. SMEM: Ah/Al [64][264], Bh/Bl [256][72]; C reuses A.
// ---------------------------------------------------------------------------
__global__ __launch_bounds__(256, 1) void gemm_wmma_kernel(
    const float* __restrict__ feat, int n)
{
    extern __shared__ char smem[];
    __nv_bfloat16* Ah = reinterpret_cast<__nv_bfloat16*>(smem);      // 33792 B
    __nv_bfloat16* Al = Ah + M_TILE * LDA;                           // 33792 B
    __nv_bfloat16* Bh = Al + M_TILE * LDA;                           // 36864 B
    __nv_bfloat16* Bl = Bh + UNITS * LDB;                            // 36864 B
    float* C = reinterpret_cast<float*>(smem);                       // reuse A

    const int tid = threadIdx.x;
    const int wid = tid >> 5, lane = tid & 31;
    const int row0 = blockIdx.x * M_TILE;
    const int nrows = min(M_TILE, n - row0);

    // --- stage A: fp32 -> bf16 hi/lo, padded rows ---
#pragma unroll
    for (int it = 0; it < 16; it++) {
        const int j = it * 256 + tid;          // float4 id, 0..4095
        const int r = j >> 6;                  // row 0..63
        const int c4 = (j & 63) << 2;
        float4 v = make_float4(0.f, 0.f, 0.f, 0.f);
        if (r < nrows)
            v = reinterpret_cast<const float4*>(feat + (size_t)(row0 + r) * F_DIM)[j & 63];
        const __nv_bfloat16 h0 = __float2bfloat16(v.x);
        const __nv_bfloat16 h1 = __float2bfloat16(v.y);
        const __nv_bfloat16 h2 = __float2bfloat16(v.z);
        const __nv_bfloat16 h3 = __float2bfloat16(v.w);
        __nv_bfloat162 ph0; ph0.x = h0; ph0.y = h1;
        __nv_bfloat162 ph1; ph1.x = h2; ph1.y = h3;
        __nv_bfloat162 pl0, pl1;
        pl0.x = __float2bfloat16(v.x - __bfloat162float(h0));
        pl0.y = __float2bfloat16(v.y - __bfloat162float(h1));
        pl1.x = __float2bfloat16(v.z - __bfloat162float(h2));
        pl1.y = __float2bfloat16(v.w - __bfloat162float(h3));
        reinterpret_cast<__nv_bfloat162*>(Ah + r * LDA + c4)[0] = ph0;
        reinterpret_cast<__nv_bfloat162*>(Ah + r * LDA + c4)[1] = ph1;
        reinterpret_cast<__nv_bfloat162*>(Al + r * LDA + c4)[0] = pl0;
        reinterpret_cast<__nv_bfloat162*>(Al + r * LDA + c4)[1] = pl1;
    }

    const int rg = wid >> 2;            // 0..1  (row group, 32 rows)
    const int cg = wid & 3;             // 0..3  (col group, 64 cols)

    wmma::fragment<wmma::accumulator, 16, 16, 16, float> acc[2][4];
#pragma unroll
    for (int i = 0; i < 2; i++)
#pragma unroll
        for (int j = 0; j < 4; j++) wmma::fill_fragment(acc[i][j], 0.0f);

    // --- mainloop over 4 K-chunks of 64 ---
    for (int kc = 0; kc < F_DIM; kc += KC) {
        __syncthreads();   // protect B smem from previous chunk's readers
        // cooperative stage of B chunk: 256 n-rows x 64 k, hi+lo
        // thread t loads uint4 (8 bf16): 8 threads per n-row, fully coalesced
#pragma unroll
        for (int it = 0; it < 8; it++) {
            const int g = it * 256 + tid;       // 0..2047
            const int nn = g >> 3;              // 0..255
            const int k8 = (g & 7) << 3;        // 0,8,..56
            const size_t goff = (size_t)nn * F_DIM + kc + k8;
            *reinterpret_cast<uint4*>(Bh + nn * LDB + k8) =
                *reinterpret_cast<const uint4*>(g_Wh + goff);
            *reinterpret_cast<uint4*>(Bl + nn * LDB + k8) =
                *reinterpret_cast<const uint4*>(g_Wl + goff);
        }
        __syncthreads();

#pragma unroll
        for (int ks = 0; ks < KC; ks += 16) {
            wmma::fragment<wmma::matrix_a, 16, 16, 16, __nv_bfloat16, wmma::row_major> fah[2], fal[2];
#pragma unroll
            for (int i = 0; i < 2; i++) {
                const int r = rg * 32 + i * 16;
                wmma::load_matrix_sync(fah[i], Ah + r * LDA + kc + ks, LDA);
                wmma::load_matrix_sync(fal[i], Al + r * LDA + kc + ks, LDA);
            }
#pragma unroll
            for (int j = 0; j < 4; j++) {
                const int ncol = cg * 64 + j * 16;
                wmma::fragment<wmma::matrix_b, 16, 16, 16, __nv_bfloat16, wmma::col_major> fbh, fbl;
                wmma::load_matrix_sync(fbh, Bh + ncol * LDB + ks, LDB);
                wmma::load_matrix_sync(fbl, Bl + ncol * LDB + ks, LDB);
#pragma unroll
                for (int i = 0; i < 2; i++) {
                    wmma::mma_sync(acc[i][j], fah[i], fbh, acc[i][j]);
                    wmma::mma_sync(acc[i][j], fah[i], fbl, acc[i][j]);
                    wmma::mma_sync(acc[i][j], fal[i], fbh, acc[i][j]);
                }
            }
        }
    }
    __syncthreads();   // A smem no longer needed; reuse as C

#pragma unroll
    for (int i = 0; i < 2; i++)
#pragma unroll
        for (int j = 0; j < 4; j++)
            wmma::store_matrix_sync(C + (rg * 32 + i * 16) * UNITS + cg * 64 + j * 16,
                                    acc[i][j], UNITS, wmma::mem_row_major);
    __syncthreads();

    // --- epilogue: activations, attention, KL, g_x ---
    float kl = 0.f;
#pragma unroll
    for (int it = 0; it < 32; it++) {
        const int idx = it * 256 + tid;
        const int r = idx >> 7;
        const int d = idx & 127;
        if (r < nrows) {
            const float hm = C[r * UNITS + d];
            const float hv = C[r * UNITS + DIM + d];
            const float m = elu_f(hm);
            const float v = hv > 0.f ? hv : 0.f;
            const float att = fast_exp(-v);
            kl += m * m + v - logf(1e-8f + v) - 1.f;
            const size_t base = (size_t)(row0 + r) * UNITS;
            g_x[base + d]       = m * att;
            g_x[base + DIM + d] = v * att * att;
        }
    }
    kl *= 0.5f / (float)DIM;

    __shared__ float kl_red[8];
#pragma unroll
    for (int off = 16; off > 0; off >>= 1)
        kl += __shfl_down_sync(0xFFFFFFFFu, kl, off);
    if (lane == 0) kl_red[wid] = kl;
    __syncthreads();
    if (tid == 0) {
        float s = 0.f;
#pragma unroll
        for (int i = 0; i < 8; i++) s += kl_red[i];
        atomicAdd(&g_kl, s);
    }
}

// ---------------------------------------------------------------------------
// Kernel 3: fused dual SpMM, 2 warps per node, 8-way unrolled gathers
// ---------------------------------------------------------------------------
__global__ void spmm_kernel(
    const int* __restrict__ col,
    const float* __restrict__ a1,
    const float* __restrict__ a2,
    float* __restrict__ out,
    int n, int write_kl)
{
    const int gtid = blockIdx.x * blockDim.x + threadIdx.x;
    if (gtid == 0 && write_kl) out[(size_t)n * UNITS] = g_kl;

    const int work = gtid >> 5;
    const int node = work >> 1;
    const int half = work & 1;
    const int lane = threadIdx.x & 31;
    if (node >= n) return;

    const int s = g_rowptr[node];
    const int e = g_rowptr[node + 1];
    const float* __restrict__ av = half ? a2 : a1;
    const float* __restrict__ xb = g_x + half * DIM;

    float4 acc = make_float4(0.f, 0.f, 0.f, 0.f);
    int i = s;
    for (; i + 7 < e; i += 8) {
        int   c[8];
        float w[8];
#pragma unroll
        for (int u = 0; u < 8; u++) { c[u] = __ldg(&col[i + u]); w[u] = __ldg(&av[i + u]); }
        float4 x[8];
#pragma unroll
        for (int u = 0; u < 8; u++)
            x[u] = __ldg(&reinterpret_cast<const float4*>(xb + (size_t)c[u] * UNITS)[lane]);
#pragma unroll
        for (int u = 0; u < 8; u++) {
            acc.x = fmaf(w[u], x[u].x, acc.x); acc.y = fmaf(w[u], x[u].y, acc.y);
            acc.z = fmaf(w[u], x[u].z, acc.z); acc.w = fmaf(w[u], x[u].w, acc.w);
        }
    }
    for (; i < e; i++) {
        const int c0 = __ldg(&col[i]);
        const float w0 = __ldg(&av[i]);
        const float4 x0 = __ldg(&reinterpret_cast<const float4*>(xb + (size_t)c0 * UNITS)[lane]);
        acc.x = fmaf(w0, x0.x, acc.x); acc.y = fmaf(w0, x0.y, acc.y);
        acc.z = fmaf(w0, x0.z, acc.z); acc.w = fmaf(w0, x0.w, acc.w);
    }
    reinterpret_cast<float4*>(out + (size_t)node * UNITS + half * DIM)[lane] = acc;
}

// ---------------------------------------------------------------------------
extern "C" void kernel_launch(void* const* d_in, const int* in_sizes, int n_in,
                              void* d_out, int out_size) {
    const float* feat = (const float*)d_in[0];
    const float* W    = (const float*)d_in[1];
    const int*   row  = (const int*)d_in[2];
    const int*   col  = (const int*)d_in[3];
    const float* a1   = (const float*)d_in[4];
    const float* a2   = (const float*)d_in[5];
    float* out = (float*)d_out;

    const int n = in_sizes[0] / F_DIM;
    const int e = in_sizes[2];
    const int write_kl = (out_size > n * UNITS) ? 1 : 0;

    {   // CSR row pointers
        const int threads = 256;
        build_rowptr_kernel<<<(e + 1 + threads - 1) / threads, threads>>>(row, n, e);
    }
    {   // W split to bf16 hi/lo, transposed
        const int threads = 256;
        wsplit_kernel<<<(UNITS * F_DIM + threads - 1) / threads, threads>>>(W);
    }
    {   // WMMA GEMM + epilogue
        const int smem_total = 2 * M_TILE * LDA * 2 + 2 * UNITS * LDB * 2; // 141312
        cudaFuncSetAttribute(gemm_wmma_kernel,
                             cudaFuncAttributeMaxDynamicSharedMemorySize, smem_total);
        gemm_wmma_kernel<<<(n + M_TILE - 1) / M_TILE, 256, smem_total>>>(feat, n);
    }
    {   // dual SpMM
        const int threads = 256;
        const int warps_needed = 2 * n;
        spmm_kernel<<<(warps_needed + 7) / 8, threads>>>(col, a1, a2, out, n, write_kl);
    }
}

// round 6
// speedup vs baseline: 1.6038x; 1.0626x over previous
#include <cuda_runtime.h>
#include <cuda_bf16.h>
#include <mma.h>
#include <math.h>
#include <stdint.h>

using namespace nvcuda;

// Problem constants: N=100000, F=256, UNITS=256, DIM=128
#define F_DIM   256
#define UNITS   256
#define DIM     128
#define N_MAX   100000
#define M_TILE  64
#define LDA     264          // padded A smem leading dim (elements)
#define LDB     40           // padded B smem leading dim (elements, KC=32 + 8)
#define KC      32           // K chunk staged per iteration

// Scratch
__device__ float         g_x[(size_t)N_MAX * UNITS];   // ~102.4 MB
__device__ int           g_rowptr[N_MAX + 1];
__device__ float         g_kl;
__device__ __nv_bfloat16 g_Wh[UNITS * F_DIM];          // W^T hi, [n][k]
__device__ __nv_bfloat16 g_Wl[UNITS * F_DIM];          // W^T lo, [n][k]

// ---------------------------------------------------------------------------
// MUFU-free exp (x <= 0) and elu
// ---------------------------------------------------------------------------
__device__ __forceinline__ float fast_exp(float x) {
    x = fmaxf(x, -80.f);
    const float t = x * 1.4426950408889634f;
    const float nf = rintf(t);
    const float f = t - nf;
    float p = 1.5253232e-5f;
    p = fmaf(p, f, 1.54035304e-4f);
    p = fmaf(p, f, 1.33335581e-3f);
    p = fmaf(p, f, 9.61812911e-3f);
    p = fmaf(p, f, 5.55041087e-2f);
    p = fmaf(p, f, 2.40226507e-1f);
    p = fmaf(p, f, 6.93147181e-1f);
    p = fmaf(p, f, 1.0f);
    return __int_as_float(__float_as_int(p) + (((int)nf) << 23));
}
__device__ __forceinline__ float elu_f(float x) {
    if (x > 0.f) return x;
    if (x > -0.5f) {
        float p = 1.98412698e-4f;
        p = fmaf(p, x, 1.38888889e-3f);
        p = fmaf(p, x, 8.33333333e-3f);
        p = fmaf(p, x, 4.16666667e-2f);
        p = fmaf(p, x, 1.66666667e-1f);
        p = fmaf(p, x, 0.5f);
        p = fmaf(p, x, 1.0f);
        return x * p;
    }
    return fast_exp(x) - 1.0f;
}

// ---------------------------------------------------------------------------
// Kernel 1: CSR row_ptr via boundary scatter
// ---------------------------------------------------------------------------
__global__ void build_rowptr_kernel(const int* __restrict__ row, int n, int e) {
    int i = blockIdx.x * blockDim.x + threadIdx.x;
    if (i == 0) g_kl = 0.0f;
    if (i > e) return;
    int prev = (i == 0) ? -1 : row[i - 1];
    int cur  = (i == e) ? n  : row[i];
    for (int j = prev + 1; j <= cur; j++) g_rowptr[j] = i;
}

// ---------------------------------------------------------------------------
// Kernel 1b: split W (fp32 [K,N]) into transposed bf16 hi/lo [N,K]
// ---------------------------------------------------------------------------
__global__ void wsplit_kernel(const float* __restrict__ W) {
    int i = blockIdx.x * blockDim.x + threadIdx.x;
    if (i >= UNITS * F_DIM) return;
    const int nn = i / F_DIM, kk = i % F_DIM;
    const float w = W[kk * UNITS + nn];
    const __nv_bfloat16 h = __float2bfloat16(w);
    g_Wh[i] = h;
    g_Wl[i] = __float2bfloat16(w - __bfloat162float(h));
}

// ---------------------------------------------------------------------------
// Kernel 2: WMMA bf16x3 GEMM. KC=32 chunks -> 106KB smem -> 2 CTAs/SM.
// CTA: 256 threads (8 warps); warp (rg,cg) owns 32 rows x 64 cols.
// SMEM: Ah/Al [64][264], Bh/Bl [256][40]; C reuses A region.
// ---------------------------------------------------------------------------
__global__ __launch_bounds__(256, 2) void gemm_wmma_kernel(
    const float* __restrict__ feat, int n)
{
    extern __shared__ char smem[];
    __nv_bfloat16* Ah = reinterpret_cast<__nv_bfloat16*>(smem);      // 33792 B
    __nv_bfloat16* Al = Ah + M_TILE * LDA;                           // 33792 B
    __nv_bfloat16* Bh = Al + M_TILE * LDA;                           // 20480 B
    __nv_bfloat16* Bl = Bh + UNITS * LDB;                            // 20480 B
    float* C = reinterpret_cast<float*>(smem);                       // reuse A

    const int tid = threadIdx.x;
    const int wid = tid >> 5, lane = tid & 31;
    const int row0 = blockIdx.x * M_TILE;
    const int nrows = min(M_TILE, n - row0);

    // --- stage A: fp32 -> bf16 hi/lo, padded rows ---
#pragma unroll
    for (int it = 0; it < 16; it++) {
        const int j = it * 256 + tid;          // float4 id, 0..4095
        const int r = j >> 6;                  // row 0..63
        const int c4 = (j & 63) << 2;
        float4 v = make_float4(0.f, 0.f, 0.f, 0.f);
        if (r < nrows)
            v = reinterpret_cast<const float4*>(feat + (size_t)(row0 + r) * F_DIM)[j & 63];
        const __nv_bfloat16 h0 = __float2bfloat16(v.x);
        const __nv_bfloat16 h1 = __float2bfloat16(v.y);
        const __nv_bfloat16 h2 = __float2bfloat16(v.z);
        const __nv_bfloat16 h3 = __float2bfloat16(v.w);
        __nv_bfloat162 ph0; ph0.x = h0; ph0.y = h1;
        __nv_bfloat162 ph1; ph1.x = h2; ph1.y = h3;
        __nv_bfloat162 pl0, pl1;
        pl0.x = __float2bfloat16(v.x - __bfloat162float(h0));
        pl0.y = __float2bfloat16(v.y - __bfloat162float(h1));
        pl1.x = __float2bfloat16(v.z - __bfloat162float(h2));
        pl1.y = __float2bfloat16(v.w - __bfloat162float(h3));
        reinterpret_cast<__nv_bfloat162*>(Ah + r * LDA + c4)[0] = ph0;
        reinterpret_cast<__nv_bfloat162*>(Ah + r * LDA + c4)[1] = ph1;
        reinterpret_cast<__nv_bfloat162*>(Al + r * LDA + c4)[0] = pl0;
        reinterpret_cast<__nv_bfloat162*>(Al + r * LDA + c4)[1] = pl1;
    }

    const int rg = wid >> 2;            // 0..1  (row group, 32 rows)
    const int cg = wid & 3;             // 0..3  (col group, 64 cols)

    wmma::fragment<wmma::accumulator, 16, 16, 16, float> acc[2][4];
#pragma unroll
    for (int i = 0; i < 2; i++)
#pragma unroll
        for (int j = 0; j < 4; j++) wmma::fill_fragment(acc[i][j], 0.0f);

    // --- mainloop over 8 K-chunks of 32 ---
    for (int kc = 0; kc < F_DIM; kc += KC) {
        __syncthreads();   // protect B smem from previous chunk's readers
        // stage B chunk: 256 n-rows x 32 k, hi+lo; uint4 per thread (8 bf16)
#pragma unroll
        for (int it = 0; it < 4; it++) {
            const int g = it * 256 + tid;       // 0..1023
            const int nn = g >> 2;              // 0..255
            const int k8 = (g & 3) << 3;        // 0,8,16,24
            const size_t goff = (size_t)nn * F_DIM + kc + k8;
            *reinterpret_cast<uint4*>(Bh + nn * LDB + k8) =
                *reinterpret_cast<const uint4*>(g_Wh + goff);
            *reinterpret_cast<uint4*>(Bl + nn * LDB + k8) =
                *reinterpret_cast<const uint4*>(g_Wl + goff);
        }
        __syncthreads();

#pragma unroll
        for (int ks = 0; ks < KC; ks += 16) {
            wmma::fragment<wmma::matrix_a, 16, 16, 16, __nv_bfloat16, wmma::row_major> fah[2], fal[2];
#pragma unroll
            for (int i = 0; i < 2; i++) {
                const int r = rg * 32 + i * 16;
                wmma::load_matrix_sync(fah[i], Ah + r * LDA + kc + ks, LDA);
                wmma::load_matrix_sync(fal[i], Al + r * LDA + kc + ks, LDA);
            }
#pragma unroll
            for (int j = 0; j < 4; j++) {
                const int ncol = cg * 64 + j * 16;
                wmma::fragment<wmma::matrix_b, 16, 16, 16, __nv_bfloat16, wmma::col_major> fbh, fbl;
                wmma::load_matrix_sync(fbh, Bh + ncol * LDB + ks, LDB);
                wmma::load_matrix_sync(fbl, Bl + ncol * LDB + ks, LDB);
#pragma unroll
                for (int i = 0; i < 2; i++) {
                    wmma::mma_sync(acc[i][j], fah[i], fbh, acc[i][j]);
                    wmma::mma_sync(acc[i][j], fah[i], fbl, acc[i][j]);
                    wmma::mma_sync(acc[i][j], fal[i], fbh, acc[i][j]);
                }
            }
        }
    }
    __syncthreads();   // A smem no longer needed; reuse as C

#pragma unroll
    for (int i = 0; i < 2; i++)
#pragma unroll
        for (int j = 0; j < 4; j++)
            wmma::store_matrix_sync(C + (rg * 32 + i * 16) * UNITS + cg * 64 + j * 16,
                                    acc[i][j], UNITS, wmma::mem_row_major);
    __syncthreads();

    // --- epilogue: activations, attention, KL, g_x ---
    float kl = 0.f;
#pragma unroll
    for (int it = 0; it < 32; it++) {
        const int idx = it * 256 + tid;
        const int r = idx >> 7;
        const int d = idx & 127;
        if (r < nrows) {
            const float hm = C[r * UNITS + d];
            const float hv = C[r * UNITS + DIM + d];
            const float m = elu_f(hm);
            const float v = hv > 0.f ? hv : 0.f;
            const float att = fast_exp(-v);
            kl += m * m + v - logf(1e-8f + v) - 1.f;
            const size_t base = (size_t)(row0 + r) * UNITS;
            g_x[base + d]       = m * att;
            g_x[base + DIM + d] = v * att * att;
        }
    }
    kl *= 0.5f / (float)DIM;

    __shared__ float kl_red[8];
#pragma unroll
    for (int off = 16; off > 0; off >>= 1)
        kl += __shfl_down_sync(0xFFFFFFFFu, kl, off);
    if (lane == 0) kl_red[wid] = kl;
    __syncthreads();
    if (tid == 0) {
        float s = 0.f;
#pragma unroll
        for (int i = 0; i < 8; i++) s += kl_red[i];
        atomicAdd(&g_kl, s);
    }
}

// ---------------------------------------------------------------------------
// Kernel 3: fused dual SpMM, 2 warps per node, 8-way unrolled gathers.
// Streaming hints: col/a arrays read-once (__ldcs), output evict-first
// (__stcs) so L2 stays dedicated to the g_x gather table.
// ---------------------------------------------------------------------------
__global__ void spmm_kernel(
    const int* __restrict__ col,
    const float* __restrict__ a1,
    const float* __restrict__ a2,
    float* __restrict__ out,
    int n, int write_kl)
{
    const int gtid = blockIdx.x * blockDim.x + threadIdx.x;
    if (gtid == 0 && write_kl) out[(size_t)n * UNITS] = g_kl;

    const int work = gtid >> 5;
    const int node = work >> 1;
    const int half = work & 1;
    const int lane = threadIdx.x & 31;
    if (node >= n) return;

    const int s = g_rowptr[node];
    const int e = g_rowptr[node + 1];
    const float* __restrict__ av = half ? a2 : a1;
    const float* __restrict__ xb = g_x + half * DIM;

    float4 acc = make_float4(0.f, 0.f, 0.f, 0.f);
    int i = s;
    for (; i + 7 < e; i += 8) {
        int   c[8];
        float w[8];
#pragma unroll
        for (int u = 0; u < 8; u++) { c[u] = __ldcs(&col[i + u]); w[u] = __ldcs(&av[i + u]); }
        float4 x[8];
#pragma unroll
        for (int u = 0; u < 8; u++)
            x[u] = __ldg(&reinterpret_cast<const float4*>(xb + (size_t)c[u] * UNITS)[lane]);
#pragma unroll
        for (int u = 0; u < 8; u++) {
            acc.x = fmaf(w[u], x[u].x, acc.x); acc.y = fmaf(w[u], x[u].y, acc.y);
            acc.z = fmaf(w[u], x[u].z, acc.z); acc.w = fmaf(w[u], x[u].w, acc.w);
        }
    }
    for (; i < e; i++) {
        const int c0 = __ldcs(&col[i]);
        const float w0 = __ldcs(&av[i]);
        const float4 x0 = __ldg(&reinterpret_cast<const float4*>(xb + (size_t)c0 * UNITS)[lane]);
        acc.x = fmaf(w0, x0.x, acc.x); acc.y = fmaf(w0, x0.y, acc.y);
        acc.z = fmaf(w0, x0.z, acc.z); acc.w = fmaf(w0, x0.w, acc.w);
    }
    __stcs(&reinterpret_cast<float4*>(out + (size_t)node * UNITS + half * DIM)[lane], acc);
}

// ---------------------------------------------------------------------------
extern "C" void kernel_launch(void* const* d_in, const int* in_sizes, int n_in,
                              void* d_out, int out_size) {
    const float* feat = (const float*)d_in[0];
    const float* W    = (const float*)d_in[1];
    const int*   row  = (const int*)d_in[2];
    const int*   col  = (const int*)d_in[3];
    const float* a1   = (const float*)d_in[4];
    const float* a2   = (const float*)d_in[5];
    float* out = (float*)d_out;

    const int n = in_sizes[0] / F_DIM;
    const int e = in_sizes[2];
    const int write_kl = (out_size > n * UNITS) ? 1 : 0;

    {   // CSR row pointers
        const int threads = 256;
        build_rowptr_kernel<<<(e + 1 + threads - 1) / threads, threads>>>(row, n, e);
    }
    {   // W split to bf16 hi/lo, transposed
        const int threads = 256;
        wsplit_kernel<<<(UNITS * F_DIM + threads - 1) / threads, threads>>>(W);
    }
    {   // WMMA GEMM + epilogue (106KB smem -> 2 CTAs/SM)
        const int smem_total = 2 * M_TILE * LDA * 2 + 2 * UNITS * LDB * 2; // 108544
        cudaFuncSetAttribute(gemm_wmma_kernel,
                             cudaFuncAttributeMaxDynamicSharedMemorySize, smem_total);
        gemm_wmma_kernel<<<(n + M_TILE - 1) / M_TILE, 256, smem_total>>>(feat, n);
    }
    {   // dual SpMM
        const int threads = 256;
        const int warps_needed = 2 * n;
        spmm_kernel<<<(warps_needed + 7) / 8, threads>>>(col, a1, a2, out, n, write_kl);
    }
}